// round 1
// baseline (speedup 1.0000x reference)
#include <cuda_runtime.h>
#include <cstdint>

#define NN   100000
#define NE   1600000
#define KDIM 128
#define HID  128
#define OUTC 64

// ---------------- scratch (device globals; no allocation allowed) ----------
__device__ int   d_flag;                 // 1 => edge indices stored as int64
__device__ int   d_deg[NN];              // in-degree incl self loop
__device__ float d_dinv[NN];             // deg^-1/2
__device__ int   d_off[NN + 1];          // CSR offsets (by dst)
__device__ int   d_cur[NN];              // fill cursors
__device__ int   d_srcl[NE];             // CSR src lists
__device__ float d_buf1[(size_t)NN * 128];  // g1 (128w), later g2 (64w)
__device__ float d_buf2[(size_t)NN * 128];  // h1 (128w), later z (64w)

__device__ __forceinline__ int ld_idx(const int* __restrict__ p, long long i, int flag) {
    return flag ? p[2 * i] : p[i];
}

// ---------------- index width detection ------------------------------------
__global__ void k_detect(const int* __restrict__ p) {
    int nz = 0;
    for (int i = threadIdx.x; i < 512; i += 32) nz |= p[2 * i + 1];
    for (int o = 16; o; o >>= 1) nz |= __shfl_down_sync(0xffffffffu, nz, o);
    if (threadIdx.x == 0) d_flag = (nz == 0) ? 1 : 0;
}

// ---------------- degree / dinv ---------------------------------------------
__global__ void k_init_deg() {
    int v = blockIdx.x * blockDim.x + threadIdx.x;
    if (v < NN) d_deg[v] = 1;  // self loop
}

__global__ void k_degree(const int* __restrict__ p) {
    long long e = (long long)blockIdx.x * blockDim.x + threadIdx.x;
    if (e >= NE) return;
    int flag = d_flag;
    int dst = ld_idx(p, NE + e, flag);
    atomicAdd(&d_deg[dst], 1);
}

__global__ void k_dinv() {
    int v = blockIdx.x * blockDim.x + threadIdx.x;
    if (v < NN) d_dinv[v] = rsqrtf((float)d_deg[v]);
}

// ---------------- single-block exclusive scan of (deg-1) --------------------
__global__ void k_scan() {
    __shared__ int sh[1024];
    __shared__ int carry;
    int tid = threadIdx.x;
    if (tid == 0) carry = 0;
    __syncthreads();
    for (int base = 0; base < NN; base += 1024) {
        int v = base + tid;
        int val = (v < NN) ? (d_deg[v] - 1) : 0;
        sh[tid] = val;
        __syncthreads();
        #pragma unroll
        for (int off = 1; off < 1024; off <<= 1) {
            int t = (tid >= off) ? sh[tid - off] : 0;
            __syncthreads();
            sh[tid] += t;
            __syncthreads();
        }
        if (v < NN) {
            int excl = carry + sh[tid] - val;
            d_off[v] = excl;
            d_cur[v] = excl;
        }
        __syncthreads();
        if (tid == 1023) {
            carry += sh[1023];
            if (base + 1024 >= NN) d_off[NN] = carry;
        }
        __syncthreads();
    }
}

// ---------------- CSR fill ---------------------------------------------------
__global__ void k_fill(const int* __restrict__ p) {
    long long e = (long long)blockIdx.x * blockDim.x + threadIdx.x;
    if (e >= NE) return;
    int flag = d_flag;
    int src = ld_idx(p, e, flag);
    int dst = ld_idx(p, NE + e, flag);
    int pos = atomicAdd(&d_cur[dst], 1);
    d_srcl[pos] = src;
}

// ---------------- GEMM: out[r][c] = dinv[r] * sum_k A[r][k] W[k][c] ---------
// BM=32 rows per block, BN cols, K=128, BK=32. Threads = (BN/4)*8.
template <int BN, int NTHREADS>
__global__ void k_gemm(const float* __restrict__ A, const float* __restrict__ W,
                       float* __restrict__ out) {
    constexpr int BM = 32, BK = 32, K = 128;
    __shared__ float xs[BK][BM + 4];
    __shared__ float ws[BK][BN];
    const int tid = threadIdx.x;
    const int tx = tid % (BN / 4);
    const int ty = tid / (BN / 4);
    const int rowBase = blockIdx.x * BM;

    float acc[4][4];
    #pragma unroll
    for (int i = 0; i < 4; i++)
        #pragma unroll
        for (int j = 0; j < 4; j++) acc[i][j] = 0.f;

    for (int k0 = 0; k0 < K; k0 += BK) {
        // load A tile transposed: coalesced along k
        for (int i = tid; i < BM * BK; i += NTHREADS) {
            int r = i / BK;
            int kk = i % BK;
            xs[kk][r] = A[(size_t)(rowBase + r) * K + k0 + kk];
        }
        // load W tile (k-major already)
        for (int i = tid; i < BK * BN / 4; i += NTHREADS) {
            int kk = i / (BN / 4);
            int n4 = (i % (BN / 4)) * 4;
            *(float4*)&ws[kk][n4] = *(const float4*)&W[(size_t)(k0 + kk) * BN + n4];
        }
        __syncthreads();
        #pragma unroll
        for (int kk = 0; kk < BK; kk++) {
            float4 a = *(const float4*)&xs[kk][ty * 4];
            float4 b = *(const float4*)&ws[kk][tx * 4];
            acc[0][0] += a.x * b.x; acc[0][1] += a.x * b.y; acc[0][2] += a.x * b.z; acc[0][3] += a.x * b.w;
            acc[1][0] += a.y * b.x; acc[1][1] += a.y * b.y; acc[1][2] += a.y * b.z; acc[1][3] += a.y * b.w;
            acc[2][0] += a.z * b.x; acc[2][1] += a.z * b.y; acc[2][2] += a.z * b.z; acc[2][3] += a.z * b.w;
            acc[3][0] += a.w * b.x; acc[3][1] += a.w * b.y; acc[3][2] += a.w * b.z; acc[3][3] += a.w * b.w;
        }
        __syncthreads();
    }
    #pragma unroll
    for (int i = 0; i < 4; i++) {
        int row = rowBase + ty * 4 + i;
        float dv = d_dinv[row];
        float4 v = make_float4(acc[i][0] * dv, acc[i][1] * dv, acc[i][2] * dv, acc[i][3] * dv);
        *(float4*)&out[(size_t)row * BN + tx * 4] = v;
    }
}

// ---------------- layer-1 aggregate: warp per node, 128 cols ----------------
__global__ void k_gather1(const float* __restrict__ b1) {
    int warp = (blockIdx.x * blockDim.x + threadIdx.x) >> 5;
    int lane = threadIdx.x & 31;
    if (warp >= NN) return;
    const float4* g = (const float4*)d_buf1;
    float4 acc = g[(size_t)warp * 32 + lane];  // self-loop term
    int s = d_off[warp], e = d_off[warp + 1];
    for (int i = s; i < e; i += 32) {
        int u = (i + lane < e) ? d_srcl[i + lane] : 0;
        int m = min(32, e - i);
        for (int j = 0; j < m; j++) {
            int uu = __shfl_sync(0xffffffffu, u, j);
            float4 t = g[(size_t)uu * 32 + lane];
            acc.x += t.x; acc.y += t.y; acc.z += t.z; acc.w += t.w;
        }
    }
    float dv = d_dinv[warp];
    float4 bb = ((const float4*)b1)[lane];
    float4 h;
    h.x = fmaxf(dv * acc.x + bb.x, 0.f);
    h.y = fmaxf(dv * acc.y + bb.y, 0.f);
    h.z = fmaxf(dv * acc.z + bb.z, 0.f);
    h.w = fmaxf(dv * acc.w + bb.w, 0.f);
    ((float4*)d_buf2)[(size_t)warp * 32 + lane] = h;
}

// ---------------- layer-2 aggregate: warp per node, 64 cols ------------------
__global__ void k_gather2(const float* __restrict__ b2) {
    int warp = (blockIdx.x * blockDim.x + threadIdx.x) >> 5;
    int lane = threadIdx.x & 31;
    if (warp >= NN) return;
    const float2* g = (const float2*)d_buf1;  // g2 lives in low N*64 floats
    float2 acc = g[(size_t)warp * 32 + lane];
    int s = d_off[warp], e = d_off[warp + 1];
    for (int i = s; i < e; i += 32) {
        int u = (i + lane < e) ? d_srcl[i + lane] : 0;
        int m = min(32, e - i);
        for (int j = 0; j < m; j++) {
            int uu = __shfl_sync(0xffffffffu, u, j);
            float2 t = g[(size_t)uu * 32 + lane];
            acc.x += t.x; acc.y += t.y;
        }
    }
    float dv = d_dinv[warp];
    float2 bb = ((const float2*)b2)[lane];
    float2 z;
    z.x = dv * acc.x + bb.x;
    z.y = dv * acc.y + bb.y;
    ((float2*)d_buf2)[(size_t)warp * 32 + lane] = z;  // z in low N*64 floats
}

// ---------------- decoder: 8 lanes per edge ----------------------------------
__global__ void k_decode(const int* __restrict__ pos32, const int* __restrict__ neg32,
                         float* __restrict__ out) {
    long long gt = (long long)blockIdx.x * blockDim.x + threadIdx.x;
    long long e = gt >> 3;
    int sub = threadIdx.x & 7;
    if (e >= 2LL * NE) return;
    const int* p;
    long long ee;
    float* o;
    if (e < NE) { p = pos32; ee = e; o = out; }
    else        { p = neg32; ee = e - NE; o = out + NE; }
    int flag = d_flag;
    int s = ld_idx(p, ee, flag);
    int d = ld_idx(p, NE + ee, flag);
    const float4* z = (const float4*)d_buf2;  // 16 float4 per row
    float4 a0 = z[(size_t)s * 16 + sub];
    float4 a1 = z[(size_t)s * 16 + 8 + sub];
    float4 c0 = z[(size_t)d * 16 + sub];
    float4 c1 = z[(size_t)d * 16 + 8 + sub];
    float pr = a0.x * c0.x + a0.y * c0.y + a0.z * c0.z + a0.w * c0.w
             + a1.x * c1.x + a1.y * c1.y + a1.z * c1.z + a1.w * c1.w;
    pr += __shfl_down_sync(0xffffffffu, pr, 4, 8);
    pr += __shfl_down_sync(0xffffffffu, pr, 2, 8);
    pr += __shfl_down_sync(0xffffffffu, pr, 1, 8);
    if (sub == 0) o[ee] = pr;
}

// ---------------- launch ------------------------------------------------------
extern "C" void kernel_launch(void* const* d_in, const int* in_sizes, int n_in,
                              void* d_out, int out_size) {
    const float* x     = (const float*)d_in[0];
    const int*   pos32 = (const int*)d_in[1];
    const int*   neg32 = (const int*)d_in[2];
    const float* W1    = (const float*)d_in[3];
    const float* b1    = (const float*)d_in[4];
    const float* W2    = (const float*)d_in[5];
    const float* b2    = (const float*)d_in[6];
    float* out = (float*)d_out;

    float *buf1, *buf2;
    cudaGetSymbolAddress((void**)&buf1, d_buf1);
    cudaGetSymbolAddress((void**)&buf2, d_buf2);

    k_detect<<<1, 32>>>(pos32);
    k_init_deg<<<(NN + 255) / 256, 256>>>();
    k_degree<<<(NE + 255) / 256, 256>>>(pos32);
    k_dinv<<<(NN + 255) / 256, 256>>>();
    k_scan<<<1, 1024>>>();
    k_fill<<<(NE + 255) / 256, 256>>>(pos32);

    // layer 1: g1 = dinv * (x @ W1)  -> buf1 ; h1 = relu(dinv*agg + b1) -> buf2
    k_gemm<128, 256><<<NN / 32, 256>>>(x, W1, buf1);
    k_gather1<<<(NN * 32 + 255) / 256, 256>>>(b1);

    // layer 2: g2 = dinv * (h1 @ W2) -> buf1(low) ; z = dinv*agg + b2 -> buf2(low)
    k_gemm<64, 128><<<NN / 32, 128>>>(buf2, W2, buf1);
    k_gather2<<<(NN * 32 + 255) / 256, 256>>>(b2);

    // decode
    long long tot = 2LL * NE * 8;
    k_decode<<<(unsigned)((tot + 255) / 256), 256>>>(pos32, neg32, out);
}

// round 2
// speedup vs baseline: 1.2603x; 1.2603x over previous
#include <cuda_runtime.h>
#include <cstdint>

#define NN   100000
#define NE   1600000
#define KDIM 128

// ---------------- scratch (device globals; no allocation allowed) ----------
__device__ int   d_flag;                 // 1 => edge indices stored as int64
__device__ int   d_deg[NN];              // in-degree incl self loop
__device__ float d_dinv[NN];             // deg^-1/2
__device__ int   d_off[NN + 1];          // CSR offsets (by dst)
__device__ int   d_cur[NN];              // fill cursors
__device__ int   d_bsum[128];            // per-block scan totals
__device__ int   d_srcl[NE];             // CSR src lists
__device__ float d_buf1[(size_t)NN * 128];  // g1 (128w), later g2 (64w)
__device__ float d_buf2[(size_t)NN * 128];  // h1 (128w), later z (64w)

__device__ __forceinline__ int ld_idx(const int* __restrict__ p, long long i, int flag) {
    return flag ? p[2 * i] : p[i];
}

// ---------------- index width detection ------------------------------------
__global__ void k_detect(const int* __restrict__ p) {
    int nz = 0;
    for (int i = threadIdx.x; i < 512; i += 32) nz |= p[2 * i + 1];
    for (int o = 16; o; o >>= 1) nz |= __shfl_down_sync(0xffffffffu, nz, o);
    if (threadIdx.x == 0) d_flag = (nz == 0) ? 1 : 0;
}

// ---------------- degree ------------------------------------------------------
__global__ void k_init_deg() {
    int v = blockIdx.x * blockDim.x + threadIdx.x;
    if (v < NN) d_deg[v] = 1;  // self loop
}

__global__ void k_degree(const int* __restrict__ p) {
    long long e = (long long)blockIdx.x * blockDim.x + threadIdx.x;
    if (e >= NE) return;
    int flag = d_flag;
    int dst = ld_idx(p, NE + e, flag);
    atomicAdd(&d_deg[dst], 1);
}

// ---------------- parallel 3-phase scan of (deg-1); also computes dinv --------
__global__ void k_scan1() {
    __shared__ int wsum[32];
    int tid = threadIdx.x, lane = tid & 31, wid = tid >> 5;
    int v = blockIdx.x * 1024 + tid;
    int deg = (v < NN) ? d_deg[v] : 1;
    if (v < NN) d_dinv[v] = rsqrtf((float)deg);
    int val = (v < NN) ? (deg - 1) : 0;
    int x = val;
    #pragma unroll
    for (int o = 1; o < 32; o <<= 1) {
        int t = __shfl_up_sync(0xffffffffu, x, o);
        if (lane >= o) x += t;
    }
    if (lane == 31) wsum[wid] = x;
    __syncthreads();
    if (wid == 0) {
        int y = wsum[lane];
        #pragma unroll
        for (int o = 1; o < 32; o <<= 1) {
            int t = __shfl_up_sync(0xffffffffu, y, o);
            if (lane >= o) y += t;
        }
        wsum[lane] = y;
    }
    __syncthreads();
    int warpoff = wid ? wsum[wid - 1] : 0;
    if (v < NN) d_off[v] = warpoff + x - val;  // partial exclusive
    if (tid == 1023) d_bsum[blockIdx.x] = wsum[31];  // block total
}

__global__ void k_scan2(int nblk) {
    __shared__ int wsum[4];
    int tid = threadIdx.x, lane = tid & 31, wid = tid >> 5;
    int val = (tid < nblk) ? d_bsum[tid] : 0;
    int x = val;
    #pragma unroll
    for (int o = 1; o < 32; o <<= 1) {
        int t = __shfl_up_sync(0xffffffffu, x, o);
        if (lane >= o) x += t;
    }
    if (lane == 31) wsum[wid] = x;
    __syncthreads();
    int off = 0;
    for (int w = 0; w < wid; w++) off += wsum[w];
    if (tid < nblk) d_bsum[tid] = off + x - val;  // exclusive
}

__global__ void k_scan3() {
    int v = blockIdx.x * blockDim.x + threadIdx.x;
    if (v == 0) d_off[NN] = NE;  // total = sum(deg-1) = NE exactly
    if (v >= NN) return;
    int o = d_off[v] + d_bsum[v >> 10];
    d_off[v] = o;
    d_cur[v] = o;
}

// ---------------- CSR fill ---------------------------------------------------
__global__ void k_fill(const int* __restrict__ p) {
    long long e = (long long)blockIdx.x * blockDim.x + threadIdx.x;
    if (e >= NE) return;
    int flag = d_flag;
    int src = ld_idx(p, e, flag);
    int dst = ld_idx(p, NE + e, flag);
    int pos = atomicAdd(&d_cur[dst], 1);
    d_srcl[pos] = src;
}

// ---------------- GEMM: out[r][c] = dinv[r] * sum_k A[r][k] W[k][c] ---------
// BM=64, BK=16, K=128. Register tile TM x TN per thread. NT = (BN/TN)*(BM/TM).
template <int BN, int TM, int TN>
__global__ void k_gemm(const float* __restrict__ A, const float* __restrict__ W,
                       float* __restrict__ out) {
    constexpr int BM = 64, BK = 16, K = 128;
    constexpr int NT = (BN / TN) * (BM / TM);
    __shared__ float xs[BK][BM + 4];
    __shared__ float ws[BK][BN];
    const int tid = threadIdx.x;
    const int tx = tid % (BN / TN);
    const int ty = tid / (BN / TN);
    const int rowBase = blockIdx.x * BM;

    float acc[TM][TN];
    #pragma unroll
    for (int i = 0; i < TM; i++)
        #pragma unroll
        for (int j = 0; j < TN; j++) acc[i][j] = 0.f;

    for (int k0 = 0; k0 < K; k0 += BK) {
        // A tile: load float4 along k, store transposed
        for (int i = tid; i < BM * BK / 4; i += NT) {
            int r = i / (BK / 4);
            int kq = i % (BK / 4);
            int row = min(rowBase + r, NN - 1);
            float4 va = *(const float4*)&A[(size_t)row * K + k0 + kq * 4];
            xs[kq * 4 + 0][r] = va.x;
            xs[kq * 4 + 1][r] = va.y;
            xs[kq * 4 + 2][r] = va.z;
            xs[kq * 4 + 3][r] = va.w;
        }
        // W tile (k-major already)
        for (int i = tid; i < BK * BN / 4; i += NT) {
            int kk = i / (BN / 4);
            int n4 = (i % (BN / 4)) * 4;
            *(float4*)&ws[kk][n4] = *(const float4*)&W[(size_t)(k0 + kk) * BN + n4];
        }
        __syncthreads();
        #pragma unroll
        for (int kk = 0; kk < BK; kk++) {
            float a[TM], b[TN];
            #pragma unroll
            for (int i = 0; i < TM; i += 4)
                *(float4*)&a[i] = *(const float4*)&xs[kk][ty * TM + i];
            #pragma unroll
            for (int j = 0; j < TN; j += 4)
                *(float4*)&b[j] = *(const float4*)&ws[kk][tx * TN + j];
            #pragma unroll
            for (int i = 0; i < TM; i++)
                #pragma unroll
                for (int j = 0; j < TN; j++) acc[i][j] += a[i] * b[j];
        }
        __syncthreads();
    }
    #pragma unroll
    for (int i = 0; i < TM; i++) {
        int row = rowBase + ty * TM + i;
        if (row < NN) {
            float dv = d_dinv[row];
            #pragma unroll
            for (int j = 0; j < TN; j += 4) {
                float4 v = make_float4(acc[i][j] * dv, acc[i][j + 1] * dv,
                                       acc[i][j + 2] * dv, acc[i][j + 3] * dv);
                *(float4*)&out[(size_t)row * BN + tx * TN + j] = v;
            }
        }
    }
}

// ---------------- layer-1 aggregate: warp per node, 128 cols ----------------
__global__ void k_gather1(const float* __restrict__ b1) {
    int warp = (blockIdx.x * blockDim.x + threadIdx.x) >> 5;
    int lane = threadIdx.x & 31;
    if (warp >= NN) return;
    const float4* g = (const float4*)d_buf1;
    float4 acc = g[(size_t)warp * 32 + lane];  // self-loop term
    int s = d_off[warp], e = d_off[warp + 1];
    for (int i = s; i < e; i += 32) {
        int u = (i + lane < e) ? d_srcl[i + lane] : 0;
        int m = min(32, e - i);
        for (int j = 0; j < m; j++) {
            int uu = __shfl_sync(0xffffffffu, u, j);
            float4 t = g[(size_t)uu * 32 + lane];
            acc.x += t.x; acc.y += t.y; acc.z += t.z; acc.w += t.w;
        }
    }
    float dv = d_dinv[warp];
    float4 bb = ((const float4*)b1)[lane];
    float4 h;
    h.x = fmaxf(dv * acc.x + bb.x, 0.f);
    h.y = fmaxf(dv * acc.y + bb.y, 0.f);
    h.z = fmaxf(dv * acc.z + bb.z, 0.f);
    h.w = fmaxf(dv * acc.w + bb.w, 0.f);
    ((float4*)d_buf2)[(size_t)warp * 32 + lane] = h;
}

// ---------------- layer-2 aggregate: warp per node, 64 cols ------------------
__global__ void k_gather2(const float* __restrict__ b2) {
    int warp = (blockIdx.x * blockDim.x + threadIdx.x) >> 5;
    int lane = threadIdx.x & 31;
    if (warp >= NN) return;
    const float2* g = (const float2*)d_buf1;  // g2 lives in low N*64 floats
    float2 acc = g[(size_t)warp * 32 + lane];
    int s = d_off[warp], e = d_off[warp + 1];
    for (int i = s; i < e; i += 32) {
        int u = (i + lane < e) ? d_srcl[i + lane] : 0;
        int m = min(32, e - i);
        for (int j = 0; j < m; j++) {
            int uu = __shfl_sync(0xffffffffu, u, j);
            float2 t = g[(size_t)uu * 32 + lane];
            acc.x += t.x; acc.y += t.y;
        }
    }
    float dv = d_dinv[warp];
    float2 bb = ((const float2*)b2)[lane];
    float2 z;
    z.x = dv * acc.x + bb.x;
    z.y = dv * acc.y + bb.y;
    ((float2*)d_buf2)[(size_t)warp * 32 + lane] = z;  // z in low N*64 floats
}

// ---------------- decoder: 8 lanes per edge ----------------------------------
__global__ void k_decode(const int* __restrict__ pos32, const int* __restrict__ neg32,
                         float* __restrict__ out) {
    long long gt = (long long)blockIdx.x * blockDim.x + threadIdx.x;
    long long e = gt >> 3;
    int sub = threadIdx.x & 7;
    if (e >= 2LL * NE) return;
    const int* p;
    long long ee;
    float* o;
    if (e < NE) { p = pos32; ee = e; o = out; }
    else        { p = neg32; ee = e - NE; o = out + NE; }
    int flag = d_flag;
    int s = ld_idx(p, ee, flag);
    int d = ld_idx(p, NE + ee, flag);
    const float4* z = (const float4*)d_buf2;  // 16 float4 per row
    float4 a0 = z[(size_t)s * 16 + sub];
    float4 a1 = z[(size_t)s * 16 + 8 + sub];
    float4 c0 = z[(size_t)d * 16 + sub];
    float4 c1 = z[(size_t)d * 16 + 8 + sub];
    float pr = a0.x * c0.x + a0.y * c0.y + a0.z * c0.z + a0.w * c0.w
             + a1.x * c1.x + a1.y * c1.y + a1.z * c1.z + a1.w * c1.w;
    pr += __shfl_down_sync(0xffffffffu, pr, 4, 8);
    pr += __shfl_down_sync(0xffffffffu, pr, 2, 8);
    pr += __shfl_down_sync(0xffffffffu, pr, 1, 8);
    if (sub == 0) o[ee] = pr;
}

// ---------------- launch ------------------------------------------------------
extern "C" void kernel_launch(void* const* d_in, const int* in_sizes, int n_in,
                              void* d_out, int out_size) {
    const float* x     = (const float*)d_in[0];
    const int*   pos32 = (const int*)d_in[1];
    const int*   neg32 = (const int*)d_in[2];
    const float* W1    = (const float*)d_in[3];
    const float* b1    = (const float*)d_in[4];
    const float* W2    = (const float*)d_in[5];
    const float* b2    = (const float*)d_in[6];
    float* out = (float*)d_out;

    float *buf1, *buf2;
    cudaGetSymbolAddress((void**)&buf1, d_buf1);
    cudaGetSymbolAddress((void**)&buf2, d_buf2);

    const int nscan = (NN + 1023) / 1024;  // 98

    k_detect<<<1, 32>>>(pos32);
    k_init_deg<<<(NN + 255) / 256, 256>>>();
    k_degree<<<(NE + 255) / 256, 256>>>(pos32);
    k_scan1<<<nscan, 1024>>>();
    k_scan2<<<1, 128>>>(nscan);
    k_scan3<<<(NN + 255) / 256, 256>>>();
    k_fill<<<(NE + 255) / 256, 256>>>(pos32);

    // layer 1: g1 = dinv * (x @ W1)  -> buf1 ; h1 = relu(dinv*agg + b1) -> buf2
    k_gemm<128, 8, 8><<<(NN + 63) / 64, 128>>>(x, W1, buf1);
    k_gather1<<<(NN * 32 + 255) / 256, 256>>>(b1);

    // layer 2: g2 = dinv * (h1 @ W2) -> buf1(low) ; z = dinv*agg + b2 -> buf2(low)
    k_gemm<64, 8, 4><<<(NN + 63) / 64, 128>>>(buf2, W2, buf1);
    k_gather2<<<(NN * 32 + 255) / 256, 256>>>(b2);

    // decode
    long long tot = 2LL * NE * 8;
    k_decode<<<(unsigned)((tot + 255) / 256), 256>>>(pos32, neg32, out);
}

// round 3
// speedup vs baseline: 1.3319x; 1.0568x over previous
#include <cuda_runtime.h>
#include <cuda_fp16.h>
#include <cstdint>

#define NN   100000
#define NE   1600000
#define KDIM 128

// ---------------- scratch (device globals; no allocation allowed) ----------
__device__ int   d_flag;                 // 1 => edge indices stored as int64
__device__ int   d_deg[NN];              // in-degree incl self loop
__device__ float d_dinv[NN];             // deg^-1/2
__device__ int   d_off[NN + 1];          // CSR offsets (by dst)
__device__ int   d_cur[NN];              // fill cursors
__device__ int   d_bsum[128];            // per-block scan totals
__device__ int   d_srcl[NE];             // CSR src lists
__device__ float d_buf1[(size_t)NN * 128];  // g1 (128w), later g2 (64w)
__device__ float d_buf2[(size_t)NN * 128];  // h1 (128w fp32), later z (64w fp16)

__device__ __forceinline__ int ld_idx(const int* __restrict__ p, long long i, int flag) {
    return flag ? p[2 * i] : p[i];
}

// ---------------- index width detection ------------------------------------
__global__ void k_detect(const int* __restrict__ p) {
    int nz = 0;
    for (int i = threadIdx.x; i < 512; i += 32) nz |= p[2 * i + 1];
    for (int o = 16; o; o >>= 1) nz |= __shfl_down_sync(0xffffffffu, nz, o);
    if (threadIdx.x == 0) d_flag = (nz == 0) ? 1 : 0;
}

// ---------------- degree ------------------------------------------------------
__global__ void k_init_deg() {
    int v = blockIdx.x * blockDim.x + threadIdx.x;
    if (v < NN) d_deg[v] = 1;  // self loop
}

__global__ void k_degree(const int* __restrict__ p) {
    long long e = (long long)blockIdx.x * blockDim.x + threadIdx.x;
    if (e >= NE) return;
    int flag = d_flag;
    int dst = ld_idx(p, NE + e, flag);
    atomicAdd(&d_deg[dst], 1);
}

// ---------------- parallel 3-phase scan of (deg-1); also computes dinv --------
__global__ void k_scan1() {
    __shared__ int wsum[32];
    int tid = threadIdx.x, lane = tid & 31, wid = tid >> 5;
    int v = blockIdx.x * 1024 + tid;
    int deg = (v < NN) ? d_deg[v] : 1;
    if (v < NN) d_dinv[v] = rsqrtf((float)deg);
    int val = (v < NN) ? (deg - 1) : 0;
    int x = val;
    #pragma unroll
    for (int o = 1; o < 32; o <<= 1) {
        int t = __shfl_up_sync(0xffffffffu, x, o);
        if (lane >= o) x += t;
    }
    if (lane == 31) wsum[wid] = x;
    __syncthreads();
    if (wid == 0) {
        int y = wsum[lane];
        #pragma unroll
        for (int o = 1; o < 32; o <<= 1) {
            int t = __shfl_up_sync(0xffffffffu, y, o);
            if (lane >= o) y += t;
        }
        wsum[lane] = y;
    }
    __syncthreads();
    int warpoff = wid ? wsum[wid - 1] : 0;
    if (v < NN) d_off[v] = warpoff + x - val;  // partial exclusive
    if (tid == 1023) d_bsum[blockIdx.x] = wsum[31];  // block total
}

__global__ void k_scan2(int nblk) {
    __shared__ int wsum[4];
    int tid = threadIdx.x, lane = tid & 31, wid = tid >> 5;
    int val = (tid < nblk) ? d_bsum[tid] : 0;
    int x = val;
    #pragma unroll
    for (int o = 1; o < 32; o <<= 1) {
        int t = __shfl_up_sync(0xffffffffu, x, o);
        if (lane >= o) x += t;
    }
    if (lane == 31) wsum[wid] = x;
    __syncthreads();
    int off = 0;
    for (int w = 0; w < wid; w++) off += wsum[w];
    if (tid < nblk) d_bsum[tid] = off + x - val;  // exclusive
}

__global__ void k_scan3() {
    int v = blockIdx.x * blockDim.x + threadIdx.x;
    if (v == 0) d_off[NN] = NE;
    if (v >= NN) return;
    int o = d_off[v] + d_bsum[v >> 10];
    d_off[v] = o;
    d_cur[v] = o;
}

// ---------------- CSR fill ---------------------------------------------------
__global__ void k_fill(const int* __restrict__ p) {
    long long e = (long long)blockIdx.x * blockDim.x + threadIdx.x;
    if (e >= NE) return;
    int flag = d_flag;
    int src = ld_idx(p, e, flag);
    int dst = ld_idx(p, NE + e, flag);
    int pos = atomicAdd(&d_cur[dst], 1);
    d_srcl[pos] = src;
}

// ---------------- GEMM: out[r][c] = [dinv[r] *] sum_k A[r][k] W[k][c] -------
// BM=64, BK=16, K=128. Register tile TM x TN per thread.
template <int BN, int TM, int TN, bool SCALE>
__global__ void k_gemm(const float* __restrict__ A, const float* __restrict__ W,
                       float* __restrict__ out) {
    constexpr int BM = 64, BK = 16, K = 128;
    constexpr int NT = (BN / TN) * (BM / TM);
    __shared__ float xs[BK][BM + 4];
    __shared__ float ws[BK][BN];
    const int tid = threadIdx.x;
    const int tx = tid % (BN / TN);
    const int ty = tid / (BN / TN);
    const int rowBase = blockIdx.x * BM;

    float acc[TM][TN];
    #pragma unroll
    for (int i = 0; i < TM; i++)
        #pragma unroll
        for (int j = 0; j < TN; j++) acc[i][j] = 0.f;

    for (int k0 = 0; k0 < K; k0 += BK) {
        for (int i = tid; i < BM * BK / 4; i += NT) {
            int r = i / (BK / 4);
            int kq = i % (BK / 4);
            int row = min(rowBase + r, NN - 1);
            float4 va = *(const float4*)&A[(size_t)row * K + k0 + kq * 4];
            xs[kq * 4 + 0][r] = va.x;
            xs[kq * 4 + 1][r] = va.y;
            xs[kq * 4 + 2][r] = va.z;
            xs[kq * 4 + 3][r] = va.w;
        }
        for (int i = tid; i < BK * BN / 4; i += NT) {
            int kk = i / (BN / 4);
            int n4 = (i % (BN / 4)) * 4;
            *(float4*)&ws[kk][n4] = *(const float4*)&W[(size_t)(k0 + kk) * BN + n4];
        }
        __syncthreads();
        #pragma unroll
        for (int kk = 0; kk < BK; kk++) {
            float a[TM], b[TN];
            #pragma unroll
            for (int i = 0; i < TM; i += 4)
                *(float4*)&a[i] = *(const float4*)&xs[kk][ty * TM + i];
            #pragma unroll
            for (int j = 0; j < TN; j += 4)
                *(float4*)&b[j] = *(const float4*)&ws[kk][tx * TN + j];
            #pragma unroll
            for (int i = 0; i < TM; i++)
                #pragma unroll
                for (int j = 0; j < TN; j++) acc[i][j] += a[i] * b[j];
        }
        __syncthreads();
    }
    #pragma unroll
    for (int i = 0; i < TM; i++) {
        int row = rowBase + ty * TM + i;
        if (row < NN) {
            float dv = SCALE ? d_dinv[row] : 1.0f;
            #pragma unroll
            for (int j = 0; j < TN; j += 4) {
                float4 v = make_float4(acc[i][j] * dv, acc[i][j + 1] * dv,
                                       acc[i][j + 2] * dv, acc[i][j + 3] * dv);
                *(float4*)&out[(size_t)row * BN + tx * TN + j] = v;
            }
        }
    }
}

// ---------------- layer-1 aggregate: warp per node, 128 cols ----------------
// g1 is UNSCALED x@W1; apply dinv[u] per message and dinv[v] on self + total.
__global__ void k_gather1(const float* __restrict__ b1) {
    int warp = (blockIdx.x * blockDim.x + threadIdx.x) >> 5;
    int lane = threadIdx.x & 31;
    if (warp >= NN) return;
    const float4* g = (const float4*)d_buf1;
    float dv = d_dinv[warp];
    float4 acc = g[(size_t)warp * 32 + lane];  // self-loop term (scaled below)
    acc.x *= dv; acc.y *= dv; acc.z *= dv; acc.w *= dv;
    int s = d_off[warp], e = d_off[warp + 1];
    for (int i = s; i < e; i += 32) {
        int u = 0; float du = 0.f;
        if (i + lane < e) { u = d_srcl[i + lane]; du = d_dinv[u]; }
        int m = min(32, e - i);
        for (int j = 0; j < m; j++) {
            int uu = __shfl_sync(0xffffffffu, u, j);
            float duu = __shfl_sync(0xffffffffu, du, j);
            float4 t = g[(size_t)uu * 32 + lane];
            acc.x += duu * t.x; acc.y += duu * t.y;
            acc.z += duu * t.z; acc.w += duu * t.w;
        }
    }
    float4 bb = ((const float4*)b1)[lane];
    float4 h;
    h.x = fmaxf(dv * acc.x + bb.x, 0.f);
    h.y = fmaxf(dv * acc.y + bb.y, 0.f);
    h.z = fmaxf(dv * acc.z + bb.z, 0.f);
    h.w = fmaxf(dv * acc.w + bb.w, 0.f);
    ((float4*)d_buf2)[(size_t)warp * 32 + lane] = h;
}

// ---------------- layer-2 aggregate: warp per node, 64 cols; z -> fp16 -------
__global__ void k_gather2(const float* __restrict__ b2) {
    int warp = (blockIdx.x * blockDim.x + threadIdx.x) >> 5;
    int lane = threadIdx.x & 31;
    if (warp >= NN) return;
    const float2* g = (const float2*)d_buf1;  // g2 pre-scaled by dinv[u]
    float2 acc = g[(size_t)warp * 32 + lane];
    int s = d_off[warp], e = d_off[warp + 1];
    for (int i = s; i < e; i += 32) {
        int u = (i + lane < e) ? d_srcl[i + lane] : 0;
        int m = min(32, e - i);
        for (int j = 0; j < m; j++) {
            int uu = __shfl_sync(0xffffffffu, u, j);
            float2 t = g[(size_t)uu * 32 + lane];
            acc.x += t.x; acc.y += t.y;
        }
    }
    float dv = d_dinv[warp];
    float2 bb = ((const float2*)b2)[lane];
    float2 z = make_float2(dv * acc.x + bb.x, dv * acc.y + bb.y);
    __half2* zh = (__half2*)d_buf2;  // node row = 32 half2 = 128B
    zh[(size_t)warp * 32 + lane] = __float22half2_rn(z);
}

// ---------------- decoder: 8 lanes per edge, fp16 z, fp32 accumulate ---------
__global__ void k_decode(const int* __restrict__ pos32, const int* __restrict__ neg32,
                         float* __restrict__ out) {
    long long gt = (long long)blockIdx.x * blockDim.x + threadIdx.x;
    long long e = gt >> 3;
    int sub = threadIdx.x & 7;
    if (e >= 2LL * NE) return;
    const int* p;
    long long ee;
    float* o;
    if (e < NE) { p = pos32; ee = e; o = out; }
    else        { p = neg32; ee = e - NE; o = out + NE; }
    int flag = d_flag;
    int s = ld_idx(p, ee, flag);
    int d = ld_idx(p, NE + ee, flag);
    const uint4* z4 = (const uint4*)d_buf2;  // node row = 8 uint4 (64 halves)
    uint4 a = z4[(size_t)s * 8 + sub];
    uint4 c = z4[(size_t)d * 8 + sub];
    const __half2* ah = reinterpret_cast<const __half2*>(&a);
    const __half2* ch = reinterpret_cast<const __half2*>(&c);
    float pr = 0.f;
    #pragma unroll
    for (int i = 0; i < 4; i++) {
        float2 fa = __half22float2(ah[i]);
        float2 fc = __half22float2(ch[i]);
        pr += fa.x * fc.x + fa.y * fc.y;
    }
    pr += __shfl_down_sync(0xffffffffu, pr, 4, 8);
    pr += __shfl_down_sync(0xffffffffu, pr, 2, 8);
    pr += __shfl_down_sync(0xffffffffu, pr, 1, 8);
    if (sub == 0) o[ee] = pr;
}

// ---------------- launch ------------------------------------------------------
extern "C" void kernel_launch(void* const* d_in, const int* in_sizes, int n_in,
                              void* d_out, int out_size) {
    const float* x     = (const float*)d_in[0];
    const int*   pos32 = (const int*)d_in[1];
    const int*   neg32 = (const int*)d_in[2];
    const float* W1    = (const float*)d_in[3];
    const float* b1    = (const float*)d_in[4];
    const float* W2    = (const float*)d_in[5];
    const float* b2    = (const float*)d_in[6];
    float* out = (float*)d_out;

    float *buf1, *buf2;
    cudaGetSymbolAddress((void**)&buf1, d_buf1);
    cudaGetSymbolAddress((void**)&buf2, d_buf2);

    const int nscan = (NN + 1023) / 1024;  // 98

    // Main chain on the (captured) default stream; fork a side stream for GEMM1.
    cudaStream_t cap = cudaStreamPerThread;
    cudaStream_t s2;
    cudaStreamCreate(&s2);
    cudaEvent_t e0, e1;
    cudaEventCreateWithFlags(&e0, cudaEventDisableTiming);
    cudaEventCreateWithFlags(&e1, cudaEventDisableTiming);

    cudaEventRecord(e0, cap);
    cudaStreamWaitEvent(s2, e0, 0);

    // side stream: g1 = x @ W1 (unscaled) -> buf1   (~90us, FFMA-bound)
    k_gemm<128, 8, 8, false><<<(NN + 63) / 64, 128, 0, s2>>>(x, W1, buf1);

    // main stream: CSR build (~55us, L2/atomic-bound) — overlaps GEMM1
    k_detect<<<1, 32, 0, cap>>>(pos32);
    k_init_deg<<<(NN + 255) / 256, 256, 0, cap>>>();
    k_degree<<<(NE + 255) / 256, 256, 0, cap>>>(pos32);
    k_scan1<<<nscan, 1024, 0, cap>>>();
    k_scan2<<<1, 128, 0, cap>>>(nscan);
    k_scan3<<<(NN + 255) / 256, 256, 0, cap>>>();
    k_fill<<<(NE + 255) / 256, 256, 0, cap>>>(pos32);

    cudaEventRecord(e1, s2);
    cudaStreamWaitEvent(cap, e1, 0);

    // layer 1 aggregate: h1 = relu(dinv*(sum dinv_u*g_u + dinv*g_v) + b1) -> buf2
    k_gather1<<<(NN * 32 + 255) / 256, 256, 0, cap>>>(b1);

    // layer 2: g2 = dinv * (h1 @ W2) -> buf1(low); z = (dinv*agg + b2) fp16 -> buf2
    k_gemm<64, 8, 4, true><<<(NN + 63) / 64, 128, 0, cap>>>(buf2, W2, buf1);
    k_gather2<<<(NN * 32 + 255) / 256, 256, 0, cap>>>(b2);

    // decode
    long long tot = 2LL * NE * 8;
    k_decode<<<(unsigned)((tot + 255) / 256), 256, 0, cap>>>(pos32, neg32, out);

    cudaEventDestroy(e0);
    cudaEventDestroy(e1);
    cudaStreamDestroy(s2);
}

// round 4
// speedup vs baseline: 1.4533x; 1.0911x over previous
#include <cuda_runtime.h>
#include <cuda_fp16.h>
#include <cstdint>

#define NN   100000
#define NE   1600000
#define KDIM 128

// ---------------- scratch (device globals; no allocation allowed) ----------
__device__ int   d_flag;                 // 1 => edge indices stored as int64
__device__ int   d_deg[NN];              // in-degree incl self loop
__device__ float d_dinv[NN];             // deg^-1/2
__device__ int   d_off[NN + 1];          // CSR offsets (by dst)
__device__ int   d_cur[NN];              // fill cursors
__device__ int   d_bsum[128];            // per-block scan totals
__device__ int   d_srcl[NE];             // CSR src lists
__device__ float d_buf1[(size_t)NN * 64];   // g1 fp16 (128w) / g2 fp16 (64w)
__device__ float d_buf2[(size_t)NN * 128];  // h1 fp32 (128w), later z fp16 (64w)

__device__ __forceinline__ int ld_idx(const int* __restrict__ p, long long i, int flag) {
    return flag ? p[2 * i] : p[i];
}

// ---------------- index width detection ------------------------------------
__global__ void k_detect(const int* __restrict__ p) {
    int nz = 0;
    for (int i = threadIdx.x; i < 512; i += 32) nz |= p[2 * i + 1];
    for (int o = 16; o; o >>= 1) nz |= __shfl_down_sync(0xffffffffu, nz, o);
    if (threadIdx.x == 0) d_flag = (nz == 0) ? 1 : 0;
}

// ---------------- degree ------------------------------------------------------
__global__ void k_init_deg() {
    int v = blockIdx.x * blockDim.x + threadIdx.x;
    if (v < NN) d_deg[v] = 1;  // self loop
}

__global__ void k_degree(const int* __restrict__ p) {
    long long e = (long long)blockIdx.x * blockDim.x + threadIdx.x;
    if (e >= NE) return;
    int flag = d_flag;
    int dst = ld_idx(p, NE + e, flag);
    atomicAdd(&d_deg[dst], 1);
}

// ---------------- parallel 3-phase scan of (deg-1); also computes dinv --------
__global__ void k_scan1() {
    __shared__ int wsum[32];
    int tid = threadIdx.x, lane = tid & 31, wid = tid >> 5;
    int v = blockIdx.x * 1024 + tid;
    int deg = (v < NN) ? d_deg[v] : 1;
    if (v < NN) d_dinv[v] = rsqrtf((float)deg);
    int val = (v < NN) ? (deg - 1) : 0;
    int x = val;
    #pragma unroll
    for (int o = 1; o < 32; o <<= 1) {
        int t = __shfl_up_sync(0xffffffffu, x, o);
        if (lane >= o) x += t;
    }
    if (lane == 31) wsum[wid] = x;
    __syncthreads();
    if (wid == 0) {
        int y = wsum[lane];
        #pragma unroll
        for (int o = 1; o < 32; o <<= 1) {
            int t = __shfl_up_sync(0xffffffffu, y, o);
            if (lane >= o) y += t;
        }
        wsum[lane] = y;
    }
    __syncthreads();
    int warpoff = wid ? wsum[wid - 1] : 0;
    if (v < NN) d_off[v] = warpoff + x - val;  // partial exclusive
    if (tid == 1023) d_bsum[blockIdx.x] = wsum[31];  // block total
}

__global__ void k_scan2(int nblk) {
    __shared__ int wsum[4];
    int tid = threadIdx.x, lane = tid & 31, wid = tid >> 5;
    int val = (tid < nblk) ? d_bsum[tid] : 0;
    int x = val;
    #pragma unroll
    for (int o = 1; o < 32; o <<= 1) {
        int t = __shfl_up_sync(0xffffffffu, x, o);
        if (lane >= o) x += t;
    }
    if (lane == 31) wsum[wid] = x;
    __syncthreads();
    int off = 0;
    for (int w = 0; w < wid; w++) off += wsum[w];
    if (tid < nblk) d_bsum[tid] = off + x - val;  // exclusive
}

__global__ void k_scan3() {
    int v = blockIdx.x * blockDim.x + threadIdx.x;
    if (v == 0) d_off[NN] = NE;
    if (v >= NN) return;
    int o = d_off[v] + d_bsum[v >> 10];
    d_off[v] = o;
    d_cur[v] = o;
}

// ---------------- CSR fill ---------------------------------------------------
__global__ void k_fill(const int* __restrict__ p) {
    long long e = (long long)blockIdx.x * blockDim.x + threadIdx.x;
    if (e >= NE) return;
    int flag = d_flag;
    int src = ld_idx(p, e, flag);
    int dst = ld_idx(p, NE + e, flag);
    int pos = atomicAdd(&d_cur[dst], 1);
    d_srcl[pos] = src;
}

// ---------------- GEMM: out[r][c] = dinv[r]*sum_k A[r][k] W[k][c], fp16 out --
// BM=64, BK=16, K=128. Register tile TM x TN. Output rows of BN fp16.
template <int BN, int TM, int TN>
__global__ void k_gemm_h(const float* __restrict__ A, const float* __restrict__ W,
                         __half2* __restrict__ out) {
    constexpr int BM = 64, BK = 16, K = 128;
    constexpr int NT = (BN / TN) * (BM / TM);
    __shared__ float xs[BK][BM + 4];
    __shared__ float ws[BK][BN];
    const int tid = threadIdx.x;
    const int tx = tid % (BN / TN);
    const int ty = tid / (BN / TN);
    const int rowBase = blockIdx.x * BM;

    float acc[TM][TN];
    #pragma unroll
    for (int i = 0; i < TM; i++)
        #pragma unroll
        for (int j = 0; j < TN; j++) acc[i][j] = 0.f;

    for (int k0 = 0; k0 < K; k0 += BK) {
        for (int i = tid; i < BM * BK / 4; i += NT) {
            int r = i / (BK / 4);
            int kq = i % (BK / 4);
            int row = min(rowBase + r, NN - 1);
            float4 va = *(const float4*)&A[(size_t)row * K + k0 + kq * 4];
            xs[kq * 4 + 0][r] = va.x;
            xs[kq * 4 + 1][r] = va.y;
            xs[kq * 4 + 2][r] = va.z;
            xs[kq * 4 + 3][r] = va.w;
        }
        for (int i = tid; i < BK * BN / 4; i += NT) {
            int kk = i / (BN / 4);
            int n4 = (i % (BN / 4)) * 4;
            *(float4*)&ws[kk][n4] = *(const float4*)&W[(size_t)(k0 + kk) * BN + n4];
        }
        __syncthreads();
        #pragma unroll
        for (int kk = 0; kk < BK; kk++) {
            float a[TM], b[TN];
            #pragma unroll
            for (int i = 0; i < TM; i += 4)
                *(float4*)&a[i] = *(const float4*)&xs[kk][ty * TM + i];
            #pragma unroll
            for (int j = 0; j < TN; j += 4)
                *(float4*)&b[j] = *(const float4*)&ws[kk][tx * TN + j];
            #pragma unroll
            for (int i = 0; i < TM; i++)
                #pragma unroll
                for (int j = 0; j < TN; j++) acc[i][j] += a[i] * b[j];
        }
        __syncthreads();
    }
    #pragma unroll
    for (int i = 0; i < TM; i++) {
        int row = rowBase + ty * TM + i;
        if (row < NN) {
            float dv = d_dinv[row];
            __half2 hv[TN / 2];
            #pragma unroll
            for (int j = 0; j < TN; j += 2)
                hv[j / 2] = __floats2half2_rn(acc[i][j] * dv, acc[i][j + 1] * dv);
            __half2* dst = &out[(size_t)row * (BN / 2) + tx * (TN / 2)];
            if constexpr (TN == 8) {
                *(uint4*)dst = *(uint4*)hv;      // 16B store
            } else {
                *(uint2*)dst = *(uint2*)hv;      // 8B store
            }
        }
    }
}

// ---------------- layer-1 aggregate: warp per node, 128 cols fp16 in ---------
__global__ void k_gather1(const float* __restrict__ b1) {
    int warp = (blockIdx.x * blockDim.x + threadIdx.x) >> 5;
    int lane = threadIdx.x & 31;
    if (warp >= NN) return;
    const uint2* g = (const uint2*)d_buf1;  // row = 32 lanes x 8B (4 halves)
    uint2 sv = g[(size_t)warp * 32 + lane];
    __half2 s0 = *(__half2*)&sv.x, s1 = *(__half2*)&sv.y;
    float2 f0 = __half22float2(s0), f1 = __half22float2(s1);
    float4 acc = make_float4(f0.x, f0.y, f1.x, f1.y);  // self-loop term
    int s = d_off[warp], e = d_off[warp + 1];
    for (int i = s; i < e; i += 32) {
        int u = (i + lane < e) ? d_srcl[i + lane] : 0;
        int m = min(32, e - i);
        for (int j = 0; j < m; j++) {
            int uu = __shfl_sync(0xffffffffu, u, j);
            uint2 tv = g[(size_t)uu * 32 + lane];
            float2 t0 = __half22float2(*(__half2*)&tv.x);
            float2 t1 = __half22float2(*(__half2*)&tv.y);
            acc.x += t0.x; acc.y += t0.y; acc.z += t1.x; acc.w += t1.y;
        }
    }
    float dv = d_dinv[warp];
    float4 bb = ((const float4*)b1)[lane];
    float4 h;
    h.x = fmaxf(dv * acc.x + bb.x, 0.f);
    h.y = fmaxf(dv * acc.y + bb.y, 0.f);
    h.z = fmaxf(dv * acc.z + bb.z, 0.f);
    h.w = fmaxf(dv * acc.w + bb.w, 0.f);
    ((float4*)d_buf2)[(size_t)warp * 32 + lane] = h;  // h1 fp32
}

// ---------------- layer-2 aggregate: warp per node, 64 cols fp16 in ----------
__global__ void k_gather2(const float* __restrict__ b2) {
    int warp = (blockIdx.x * blockDim.x + threadIdx.x) >> 5;
    int lane = threadIdx.x & 31;
    if (warp >= NN) return;
    const unsigned* g = (const unsigned*)d_buf1;  // row = 32 lanes x 4B (2 halves)
    float2 acc = __half22float2(*(__half2*)&g[(size_t)warp * 32 + lane]);
    int s = d_off[warp], e = d_off[warp + 1];
    for (int i = s; i < e; i += 32) {
        int u = (i + lane < e) ? d_srcl[i + lane] : 0;
        int m = min(32, e - i);
        for (int j = 0; j < m; j++) {
            int uu = __shfl_sync(0xffffffffu, u, j);
            unsigned tv = g[(size_t)uu * 32 + lane];
            float2 t = __half22float2(*(__half2*)&tv);
            acc.x += t.x; acc.y += t.y;
        }
    }
    float dv = d_dinv[warp];
    float2 bb = ((const float2*)b2)[lane];
    float2 z = make_float2(dv * acc.x + bb.x, dv * acc.y + bb.y);
    __half2* zh = (__half2*)d_buf2;  // z fp16: node row = 32 half2 = 128B
    zh[(size_t)warp * 32 + lane] = __float22half2_rn(z);
}

// ---------------- decoder: 8 lanes per edge, fp16 z, fp32 accumulate ---------
__global__ void k_decode(const int* __restrict__ pos32, const int* __restrict__ neg32,
                         float* __restrict__ out) {
    long long gt = (long long)blockIdx.x * blockDim.x + threadIdx.x;
    long long e = gt >> 3;
    int sub = threadIdx.x & 7;
    if (e >= 2LL * NE) return;
    const int* p;
    long long ee;
    float* o;
    if (e < NE) { p = pos32; ee = e; o = out; }
    else        { p = neg32; ee = e - NE; o = out + NE; }
    int flag = d_flag;
    int s = ld_idx(p, ee, flag);
    int d = ld_idx(p, NE + ee, flag);
    const uint4* z4 = (const uint4*)d_buf2;  // node row = 8 uint4 (64 halves)
    uint4 a = z4[(size_t)s * 8 + sub];
    uint4 c = z4[(size_t)d * 8 + sub];
    const __half2* ah = reinterpret_cast<const __half2*>(&a);
    const __half2* ch = reinterpret_cast<const __half2*>(&c);
    float pr = 0.f;
    #pragma unroll
    for (int i = 0; i < 4; i++) {
        float2 fa = __half22float2(ah[i]);
        float2 fc = __half22float2(ch[i]);
        pr += fa.x * fc.x + fa.y * fc.y;
    }
    pr += __shfl_down_sync(0xffffffffu, pr, 4, 8);
    pr += __shfl_down_sync(0xffffffffu, pr, 2, 8);
    pr += __shfl_down_sync(0xffffffffu, pr, 1, 8);
    if (sub == 0) o[ee] = pr;
}

// ---------------- launch ------------------------------------------------------
extern "C" void kernel_launch(void* const* d_in, const int* in_sizes, int n_in,
                              void* d_out, int out_size) {
    const float* x     = (const float*)d_in[0];
    const int*   pos32 = (const int*)d_in[1];
    const int*   neg32 = (const int*)d_in[2];
    const float* W1    = (const float*)d_in[3];
    const float* b1    = (const float*)d_in[4];
    const float* W2    = (const float*)d_in[5];
    const float* b2    = (const float*)d_in[6];
    float* out = (float*)d_out;

    __half2 *buf1;
    float *buf2;
    cudaGetSymbolAddress((void**)&buf1, d_buf1);
    cudaGetSymbolAddress((void**)&buf2, d_buf2);

    const int nscan = (NN + 1023) / 1024;  // 98

    cudaStream_t cap = cudaStreamPerThread;
    cudaStream_t s2;
    cudaStreamCreate(&s2);
    cudaEvent_t e0, e1;
    cudaEventCreateWithFlags(&e0, cudaEventDisableTiming);
    cudaEventCreateWithFlags(&e1, cudaEventDisableTiming);

    // CSR prefix chain (degree + scan) — produces dinv + offsets/cursors
    k_detect<<<1, 32, 0, cap>>>(pos32);
    k_init_deg<<<(NN + 255) / 256, 256, 0, cap>>>();
    k_degree<<<(NE + 255) / 256, 256, 0, cap>>>(pos32);
    k_scan1<<<nscan, 1024, 0, cap>>>();
    k_scan2<<<1, 128, 0, cap>>>(nscan);
    k_scan3<<<(NN + 255) / 256, 256, 0, cap>>>();

    // fork: k_fill (atomic/L2-bound) overlaps GEMM1 (FFMA-bound)
    cudaEventRecord(e0, cap);
    cudaStreamWaitEvent(s2, e0, 0);
    k_fill<<<(NE + 255) / 256, 256, 0, s2>>>(pos32);

    // g1 = dinv * (x @ W1) -> fp16 buf1
    k_gemm_h<128, 8, 8><<<(NN + 63) / 64, 128, 0, cap>>>(x, W1, buf1);

    cudaEventRecord(e1, s2);
    cudaStreamWaitEvent(cap, e1, 0);

    // h1 = relu(dinv*agg + b1) -> buf2 (fp32)
    k_gather1<<<(NN * 32 + 255) / 256, 256, 0, cap>>>(b1);

    // g2 = dinv * (h1 @ W2) -> fp16 buf1 ; z = (dinv*agg + b2) fp16 -> buf2
    k_gemm_h<64, 8, 4><<<(NN + 63) / 64, 128, 0, cap>>>(buf2, W2, buf1);
    k_gather2<<<(NN * 32 + 255) / 256, 256, 0, cap>>>(b2);

    // decode
    long long tot = 2LL * NE * 8;
    k_decode<<<(unsigned)((tot + 255) / 256), 256, 0, cap>>>(pos32, neg32, out);

    cudaEventDestroy(e0);
    cudaEventDestroy(e1);
    cudaStreamDestroy(s2);
}

// round 5
// speedup vs baseline: 1.6044x; 1.1040x over previous
#include <cuda_runtime.h>
#include <cuda_fp16.h>
#include <mma.h>
#include <cstdint>

using namespace nvcuda;

#define NN   100000
#define NE   1600000

// ---------------- scratch (device globals; no allocation allowed) ----------
__device__ int    d_flag;                // 1 => edge indices stored as int64
__device__ int    d_deg[NN];             // in-degree incl self loop
__device__ float  d_dinv[NN];            // deg^-1/2
__device__ int    d_off[NN + 1];         // CSR offsets (by dst)
__device__ int    d_cur[NN];             // fill cursors
__device__ int    d_bsum[128];           // per-block scan totals
__device__ int    d_srcl[NE];            // CSR src lists
__device__ __half d_xh[(size_t)NN * 128];  // x fp16, later h1 fp16
__device__ __half d_g[(size_t)NN * 128];   // g1 fp16 (128w) / g2 fp16 (64w)
__device__ __half d_z[(size_t)NN * 64];    // z fp16
__device__ __half d_w1h[128 * 128];
__device__ __half d_w2h[128 * 64];

__device__ __forceinline__ int ld_idx(const int* __restrict__ p, long long i, int flag) {
    return flag ? p[2 * i] : p[i];
}

// ---------------- index width detection ------------------------------------
__global__ void k_detect(const int* __restrict__ p) {
    int nz = 0;
    for (int i = threadIdx.x; i < 512; i += 32) nz |= p[2 * i + 1];
    for (int o = 16; o; o >>= 1) nz |= __shfl_down_sync(0xffffffffu, nz, o);
    if (threadIdx.x == 0) d_flag = (nz == 0) ? 1 : 0;
}

// ---------------- conversions ------------------------------------------------
__global__ void k_convx(const float* __restrict__ x) {
    long long i = (long long)blockIdx.x * blockDim.x + threadIdx.x;  // uint4 unit (8 halves)
    if (i >= (long long)NN * 128 / 8) return;
    float4 a = *(const float4*)&x[i * 8];
    float4 b = *(const float4*)&x[i * 8 + 4];
    __half2 h[4];
    h[0] = __floats2half2_rn(a.x, a.y);
    h[1] = __floats2half2_rn(a.z, a.w);
    h[2] = __floats2half2_rn(b.x, b.y);
    h[3] = __floats2half2_rn(b.z, b.w);
    *(uint4*)&d_xh[i * 8] = *(uint4*)h;
}

__global__ void k_convw(const float* __restrict__ W1, const float* __restrict__ W2) {
    int i = blockIdx.x * blockDim.x + threadIdx.x;
    if (i < 128 * 128) d_w1h[i] = __float2half(W1[i]);
    if (i < 128 * 64)  d_w2h[i] = __float2half(W2[i]);
}

// ---------------- degree ------------------------------------------------------
__global__ void k_init_deg() {
    int v = blockIdx.x * blockDim.x + threadIdx.x;
    if (v < NN) d_deg[v] = 1;  // self loop
}

__global__ void k_degree(const int* __restrict__ p) {
    long long e = (long long)blockIdx.x * blockDim.x + threadIdx.x;
    if (e >= NE) return;
    int flag = d_flag;
    int dst = ld_idx(p, NE + e, flag);
    atomicAdd(&d_deg[dst], 1);
}

// ---------------- parallel 3-phase scan of (deg-1); also computes dinv --------
__global__ void k_scan1() {
    __shared__ int wsum[32];
    int tid = threadIdx.x, lane = tid & 31, wid = tid >> 5;
    int v = blockIdx.x * 1024 + tid;
    int deg = (v < NN) ? d_deg[v] : 1;
    if (v < NN) d_dinv[v] = rsqrtf((float)deg);
    int val = (v < NN) ? (deg - 1) : 0;
    int x = val;
    #pragma unroll
    for (int o = 1; o < 32; o <<= 1) {
        int t = __shfl_up_sync(0xffffffffu, x, o);
        if (lane >= o) x += t;
    }
    if (lane == 31) wsum[wid] = x;
    __syncthreads();
    if (wid == 0) {
        int y = wsum[lane];
        #pragma unroll
        for (int o = 1; o < 32; o <<= 1) {
            int t = __shfl_up_sync(0xffffffffu, y, o);
            if (lane >= o) y += t;
        }
        wsum[lane] = y;
    }
    __syncthreads();
    int warpoff = wid ? wsum[wid - 1] : 0;
    if (v < NN) d_off[v] = warpoff + x - val;
    if (tid == 1023) d_bsum[blockIdx.x] = wsum[31];
}

__global__ void k_scan2(int nblk) {
    __shared__ int wsum[4];
    int tid = threadIdx.x, lane = tid & 31, wid = tid >> 5;
    int val = (tid < nblk) ? d_bsum[tid] : 0;
    int x = val;
    #pragma unroll
    for (int o = 1; o < 32; o <<= 1) {
        int t = __shfl_up_sync(0xffffffffu, x, o);
        if (lane >= o) x += t;
    }
    if (lane == 31) wsum[wid] = x;
    __syncthreads();
    int off = 0;
    for (int w = 0; w < wid; w++) off += wsum[w];
    if (tid < nblk) d_bsum[tid] = off + x - val;
}

__global__ void k_scan3() {
    int v = blockIdx.x * blockDim.x + threadIdx.x;
    if (v == 0) d_off[NN] = NE;
    if (v >= NN) return;
    int o = d_off[v] + d_bsum[v >> 10];
    d_off[v] = o;
    d_cur[v] = o;
}

// ---------------- CSR fill ---------------------------------------------------
__global__ void k_fill(const int* __restrict__ p) {
    long long e = (long long)blockIdx.x * blockDim.x + threadIdx.x;
    if (e >= NE) return;
    int flag = d_flag;
    int src = ld_idx(p, e, flag);
    int dst = ld_idx(p, NE + e, flag);
    int pos = atomicAdd(&d_cur[dst], 1);
    d_srcl[pos] = src;
}

// ---------------- wmma GEMM: out = dinv[r] * (A @ W), fp16 in/out, fp32 acc --
// BM=64 rows/block, K=128. BN=128 (8 warps) or BN=64 (4 warps).
template <int BN>
__global__ void k_gemm_wmma(const __half* __restrict__ A, const __half* __restrict__ Wh,
                            __half* __restrict__ out) {
    constexpr int BM = 64, K = 128;
    constexpr int NWARP = 4 * (BN / 64);
    constexpr int NT = NWARP * 32;
    __shared__ __align__(16) __half sA[BM * K];   // 16KB
    __shared__ __align__(16) __half sW[K * BN];   // 32KB / 16KB

    const int tid = threadIdx.x;
    const int wid = tid >> 5, lane = tid & 31;
    const int wm = wid & 3, wn = wid >> 2;
    const int rowBase = blockIdx.x * BM;

    // A tile: 64 x 128 halves (clamp OOB rows)
    for (int i = tid; i < BM * K / 8; i += NT) {
        int r = i >> 4;
        int c = (i & 15) * 8;
        int row = min(rowBase + r, NN - 1);
        *(uint4*)&sA[r * K + c] = *(const uint4*)&A[(size_t)row * K + c];
    }
    // W: entire K x BN
    for (int i = tid; i < K * BN / 8; i += NT)
        *(uint4*)&sW[i * 8] = *(const uint4*)&Wh[i * 8];
    __syncthreads();

    wmma::fragment<wmma::accumulator, 16, 16, 16, float> c[4];
    #pragma unroll
    for (int n = 0; n < 4; n++) wmma::fill_fragment(c[n], 0.f);

    #pragma unroll
    for (int k = 0; k < K; k += 16) {
        wmma::fragment<wmma::matrix_a, 16, 16, 16, __half, wmma::row_major> a;
        wmma::load_matrix_sync(a, &sA[(wm * 16) * K + k], K);
        #pragma unroll
        for (int n = 0; n < 4; n++) {
            wmma::fragment<wmma::matrix_b, 16, 16, 16, __half, wmma::row_major> b;
            wmma::load_matrix_sync(b, &sW[k * BN + wn * 64 + n * 16], BN);
            wmma::mma_sync(c[n], a, b, c[n]);
        }
    }
    __syncthreads();  // done with sW contents; reuse as fp32 staging

    float* stage = (float*)sW + (size_t)wid * 16 * 64;  // 4KB per warp
    #pragma unroll
    for (int n = 0; n < 4; n++)
        wmma::store_matrix_sync(stage + n * 16, c[n], 64, wmma::mem_row_major);
    __syncwarp();

    // write 16 rows x 64 cols per warp: 128 uint4 chunks, 4 per lane
    for (int i = lane; i < 128; i += 32) {
        int r = i >> 3;
        int cc = (i & 7) * 8;
        int row = rowBase + wm * 16 + r;
        if (row < NN) {
            float dv = d_dinv[row];
            __half2 hv[4];
            #pragma unroll
            for (int q = 0; q < 4; q++) {
                float v0 = stage[r * 64 + cc + 2 * q] * dv;
                float v1 = stage[r * 64 + cc + 2 * q + 1] * dv;
                hv[q] = __floats2half2_rn(v0, v1);
            }
            *(uint4*)&out[(size_t)row * BN + wn * 64 + cc] = *(uint4*)hv;
        }
    }
}

// ---------------- layer-1 aggregate: warp per node, 128 cols fp16 ------------
__global__ void k_gather1(const float* __restrict__ b1) {
    int warp = (blockIdx.x * blockDim.x + threadIdx.x) >> 5;
    int lane = threadIdx.x & 31;
    if (warp >= NN) return;
    const uint2* g = (const uint2*)d_g;  // row = 32 lanes x 8B (4 halves)
    uint2 sv = g[(size_t)warp * 32 + lane];
    float2 f0 = __half22float2(*(__half2*)&sv.x);
    float2 f1 = __half22float2(*(__half2*)&sv.y);
    float4 acc = make_float4(f0.x, f0.y, f1.x, f1.y);  // self-loop term
    int s = d_off[warp], e = d_off[warp + 1];
    for (int i = s; i < e; i += 32) {
        int u = (i + lane < e) ? d_srcl[i + lane] : 0;
        int m = min(32, e - i);
        for (int j = 0; j < m; j++) {
            int uu = __shfl_sync(0xffffffffu, u, j);
            uint2 tv = g[(size_t)uu * 32 + lane];
            float2 t0 = __half22float2(*(__half2*)&tv.x);
            float2 t1 = __half22float2(*(__half2*)&tv.y);
            acc.x += t0.x; acc.y += t0.y; acc.z += t1.x; acc.w += t1.y;
        }
    }
    float dv = d_dinv[warp];
    float4 bb = ((const float4*)b1)[lane];
    __half2 h0 = __floats2half2_rn(fmaxf(dv * acc.x + bb.x, 0.f),
                                   fmaxf(dv * acc.y + bb.y, 0.f));
    __half2 h1 = __floats2half2_rn(fmaxf(dv * acc.z + bb.z, 0.f),
                                   fmaxf(dv * acc.w + bb.w, 0.f));
    uint2 o;
    o.x = *(unsigned*)&h0;
    o.y = *(unsigned*)&h1;
    ((uint2*)d_xh)[(size_t)warp * 32 + lane] = o;  // h1 fp16 over xh
}

// ---------------- layer-2 aggregate: warp per node, 64 cols fp16 -------------
__global__ void k_gather2(const float* __restrict__ b2) {
    int warp = (blockIdx.x * blockDim.x + threadIdx.x) >> 5;
    int lane = threadIdx.x & 31;
    if (warp >= NN) return;
    const unsigned* g = (const unsigned*)d_g;  // g2: row = 32 lanes x 4B
    float2 acc = __half22float2(*(__half2*)&g[(size_t)warp * 32 + lane]);
    int s = d_off[warp], e = d_off[warp + 1];
    for (int i = s; i < e; i += 32) {
        int u = (i + lane < e) ? d_srcl[i + lane] : 0;
        int m = min(32, e - i);
        for (int j = 0; j < m; j++) {
            int uu = __shfl_sync(0xffffffffu, u, j);
            unsigned tv = g[(size_t)uu * 32 + lane];
            float2 t = __half22float2(*(__half2*)&tv);
            acc.x += t.x; acc.y += t.y;
        }
    }
    float dv = d_dinv[warp];
    float2 bb = ((const float2*)b2)[lane];
    __half2 zz = __floats2half2_rn(dv * acc.x + bb.x, dv * acc.y + bb.y);
    ((unsigned*)d_z)[(size_t)warp * 32 + lane] = *(unsigned*)&zz;
}

// ---------------- decoder: 8 lanes per edge, fp16 z, fp32 accumulate ---------
__global__ void k_decode(const int* __restrict__ pos32, const int* __restrict__ neg32,
                         float* __restrict__ out) {
    long long gt = (long long)blockIdx.x * blockDim.x + threadIdx.x;
    long long e = gt >> 3;
    int sub = threadIdx.x & 7;
    if (e >= 2LL * NE) return;
    const int* p;
    long long ee;
    float* o;
    if (e < NE) { p = pos32; ee = e; o = out; }
    else        { p = neg32; ee = e - NE; o = out + NE; }
    int flag = d_flag;
    int s = ld_idx(p, ee, flag);
    int d = ld_idx(p, NE + ee, flag);
    const uint4* z4 = (const uint4*)d_z;  // node row = 8 uint4 (64 halves)
    uint4 a = z4[(size_t)s * 8 + sub];
    uint4 c = z4[(size_t)d * 8 + sub];
    const __half2* ah = reinterpret_cast<const __half2*>(&a);
    const __half2* ch = reinterpret_cast<const __half2*>(&c);
    float pr = 0.f;
    #pragma unroll
    for (int i = 0; i < 4; i++) {
        float2 fa = __half22float2(ah[i]);
        float2 fc = __half22float2(ch[i]);
        pr += fa.x * fc.x + fa.y * fc.y;
    }
    pr += __shfl_down_sync(0xffffffffu, pr, 4, 8);
    pr += __shfl_down_sync(0xffffffffu, pr, 2, 8);
    pr += __shfl_down_sync(0xffffffffu, pr, 1, 8);
    if (sub == 0) o[ee] = pr;
}

// ---------------- launch ------------------------------------------------------
extern "C" void kernel_launch(void* const* d_in, const int* in_sizes, int n_in,
                              void* d_out, int out_size) {
    const float* x     = (const float*)d_in[0];
    const int*   pos32 = (const int*)d_in[1];
    const int*   neg32 = (const int*)d_in[2];
    const float* W1    = (const float*)d_in[3];
    const float* b1    = (const float*)d_in[4];
    const float* W2    = (const float*)d_in[5];
    const float* b2    = (const float*)d_in[6];
    float* out = (float*)d_out;

    __half *xh, *g, *z, *w1h, *w2h;
    cudaGetSymbolAddress((void**)&xh,  d_xh);
    cudaGetSymbolAddress((void**)&g,   d_g);
    cudaGetSymbolAddress((void**)&z,   d_z);
    cudaGetSymbolAddress((void**)&w1h, d_w1h);
    cudaGetSymbolAddress((void**)&w2h, d_w2h);

    const int nscan = (NN + 1023) / 1024;  // 98

    cudaStream_t cap = cudaStreamPerThread;
    cudaStream_t s2;
    cudaStreamCreate(&s2);
    cudaEvent_t e0, e_conv, e_scan, e_fill;
    cudaEventCreateWithFlags(&e0,     cudaEventDisableTiming);
    cudaEventCreateWithFlags(&e_conv, cudaEventDisableTiming);
    cudaEventCreateWithFlags(&e_scan, cudaEventDisableTiming);
    cudaEventCreateWithFlags(&e_fill, cudaEventDisableTiming);

    // fork: conversions (DRAM-bound) overlap CSR prefix chain (atomic/ALU-bound)
    cudaEventRecord(e0, cap);
    cudaStreamWaitEvent(s2, e0, 0);
    k_convx<<<(NN * 128 / 8 + 255) / 256, 256, 0, s2>>>(x);
    k_convw<<<64, 256, 0, s2>>>(W1, W2);
    cudaEventRecord(e_conv, s2);

    // main: CSR prefix chain -> dinv + offsets
    k_detect<<<1, 32, 0, cap>>>(pos32);
    k_init_deg<<<(NN + 255) / 256, 256, 0, cap>>>();
    k_degree<<<(NE + 255) / 256, 256, 0, cap>>>(pos32);
    k_scan1<<<nscan, 1024, 0, cap>>>();
    k_scan2<<<1, 128, 0, cap>>>(nscan);
    k_scan3<<<(NN + 255) / 256, 256, 0, cap>>>();
    cudaEventRecord(e_scan, cap);

    // side: fill (atomic/L2-bound) overlaps GEMM1 (tensor-bound)
    cudaStreamWaitEvent(s2, e_scan, 0);
    k_fill<<<(NE + 255) / 256, 256, 0, s2>>>(pos32);
    cudaEventRecord(e_fill, s2);

    // main: GEMM1 g1 = dinv * (x @ W1) fp16
    cudaStreamWaitEvent(cap, e_conv, 0);
    k_gemm_wmma<128><<<(NN + 63) / 64, 256, 0, cap>>>(xh, w1h, g);

    cudaStreamWaitEvent(cap, e_fill, 0);
    // h1 = relu(dinv*agg + b1) fp16 -> xh
    k_gather1<<<(NN * 32 + 255) / 256, 256, 0, cap>>>(b1);

    // GEMM2 + gather2
    k_gemm_wmma<64><<<(NN + 63) / 64, 128, 0, cap>>>(xh, w2h, g);
    k_gather2<<<(NN * 32 + 255) / 256, 256, 0, cap>>>(b2);

    // decode
    long long tot = 2LL * NE * 8;
    k_decode<<<(unsigned)((tot + 255) / 256), 256, 0, cap>>>(pos32, neg32, out);

    cudaEventDestroy(e0);
    cudaEventDestroy(e_conv);
    cudaEventDestroy(e_scan);
    cudaEventDestroy(e_fill);
    cudaStreamDestroy(s2);
}

// round 6
// speedup vs baseline: 2.2447x; 1.3991x over previous
#include <cuda_runtime.h>
#include <cuda_fp16.h>
#include <mma.h>
#include <cstdint>

using namespace nvcuda;

#define NN   100000
#define NE   1600000

// ---------------- scratch (device globals; no allocation allowed) ----------
__device__ int    d_flag;                // 1 => edge indices stored as int64
__device__ int    d_deg[NN];             // in-degree incl self loop
__device__ float  d_dinv[NN];            // deg^-1/2
__device__ int    d_off[NN + 1];         // CSR offsets (by dst)
__device__ int    d_cur[NN];             // fill cursors
__device__ int    d_bsum[128];           // per-block scan totals
__device__ int    d_srcl[NE];            // CSR src lists
__device__ __half d_xh[(size_t)NN * 128];  // x fp16, later h1 fp16
__device__ __half d_g[(size_t)NN * 128];   // g1 fp16 (128w) / g2 fp16 (64w)
__device__ __half d_z[(size_t)NN * 64];    // z fp16
__device__ __half d_w1h[128 * 128];
__device__ __half d_w2h[128 * 64];

__device__ __forceinline__ int ld_idx(const int* __restrict__ p, long long i, int flag) {
    return flag ? p[2 * i] : p[i];
}

// ---------------- fused: init_deg + weight conversion + index detect ---------
__global__ void k_pre(const int* __restrict__ p,
                      const float* __restrict__ W1, const float* __restrict__ W2) {
    int i = blockIdx.x * blockDim.x + threadIdx.x;
    if (i < NN) d_deg[i] = 1;                       // self loop
    if (i < 128 * 128) d_w1h[i] = __float2half(W1[i]);
    if (i < 128 * 64)  d_w2h[i] = __float2half(W2[i]);
    if (blockIdx.x == 0 && threadIdx.x < 32) {
        int nz = 0;
        for (int j = threadIdx.x; j < 512; j += 32) nz |= p[2 * j + 1];
        for (int o = 16; o; o >>= 1) nz |= __shfl_down_sync(0xffffffffu, nz, o);
        if (threadIdx.x == 0) d_flag = (nz == 0) ? 1 : 0;
    }
}

// ---------------- x -> fp16 ---------------------------------------------------
__global__ void k_convx(const float* __restrict__ x) {
    long long i = (long long)blockIdx.x * blockDim.x + threadIdx.x;  // 8-half unit
    if (i >= (long long)NN * 128 / 8) return;
    float4 a = *(const float4*)&x[i * 8];
    float4 b = *(const float4*)&x[i * 8 + 4];
    __half2 h[4];
    h[0] = __floats2half2_rn(a.x, a.y);
    h[1] = __floats2half2_rn(a.z, a.w);
    h[2] = __floats2half2_rn(b.x, b.y);
    h[3] = __floats2half2_rn(b.z, b.w);
    *(uint4*)&d_xh[i * 8] = *(uint4*)h;
}

// ---------------- degree ------------------------------------------------------
__global__ void k_degree(const int* __restrict__ p) {
    long long e = (long long)blockIdx.x * blockDim.x + threadIdx.x;
    if (e >= NE) return;
    int flag = d_flag;
    int dst = ld_idx(p, NE + e, flag);
    atomicAdd(&d_deg[dst], 1);
}

// ---------------- scan phase 1: per-block scan of (deg-1) + dinv --------------
__global__ void k_scan1() {
    __shared__ int wsum[32];
    int tid = threadIdx.x, lane = tid & 31, wid = tid >> 5;
    int v = blockIdx.x * 1024 + tid;
    int deg = (v < NN) ? d_deg[v] : 1;
    if (v < NN) d_dinv[v] = rsqrtf((float)deg);
    int val = (v < NN) ? (deg - 1) : 0;
    int x = val;
    #pragma unroll
    for (int o = 1; o < 32; o <<= 1) {
        int t = __shfl_up_sync(0xffffffffu, x, o);
        if (lane >= o) x += t;
    }
    if (lane == 31) wsum[wid] = x;
    __syncthreads();
    if (wid == 0) {
        int y = wsum[lane];
        #pragma unroll
        for (int o = 1; o < 32; o <<= 1) {
            int t = __shfl_up_sync(0xffffffffu, y, o);
            if (lane >= o) y += t;
        }
        wsum[lane] = y;
    }
    __syncthreads();
    int warpoff = wid ? wsum[wid - 1] : 0;
    if (v < NN) d_off[v] = warpoff + x - val;
    if (tid == 1023) d_bsum[blockIdx.x] = wsum[31];
}

// ---------------- fused scan phases 2+3: every block redundantly scans bsum ---
__global__ void k_scan23(int nblk) {
    __shared__ int sh[128];
    __shared__ int ws[4];
    int t = threadIdx.x, lane = t & 31, w = t >> 5;
    int x = 0;
    if (t < 128) {
        int val = (t < nblk) ? d_bsum[t] : 0;
        x = val;
        #pragma unroll
        for (int o = 1; o < 32; o <<= 1) {
            int tt = __shfl_up_sync(0xffffffffu, x, o);
            if (lane >= o) x += tt;
        }
        if (lane == 31) ws[w] = x;
    }
    __syncthreads();
    if (t < 128) {
        int off = 0;
        for (int q = 0; q < w; q++) off += ws[q];
        sh[t] = x + off;  // inclusive prefix of bsum
    }
    __syncthreads();
    int v = blockIdx.x * blockDim.x + t;
    if (v == 0) d_off[NN] = NE;
    if (v < NN) {
        int blk = v >> 10;
        int add = blk ? sh[blk - 1] : 0;
        int o = d_off[v] + add;
        d_off[v] = o;
        d_cur[v] = o;
    }
}

// ---------------- CSR fill ---------------------------------------------------
__global__ void k_fill(const int* __restrict__ p) {
    long long e = (long long)blockIdx.x * blockDim.x + threadIdx.x;
    if (e >= NE) return;
    int flag = d_flag;
    int src = ld_idx(p, e, flag);
    int dst = ld_idx(p, NE + e, flag);
    int pos = atomicAdd(&d_cur[dst], 1);
    d_srcl[pos] = src;
}

// ---------------- wmma GEMM, padded smem (conflict-free fragment loads) ------
// BM=64 rows/block, K=128. BN=128 (8 warps) or BN=64 (4 warps). fp32 acc.
template <int BN>
__global__ void k_gemm_wmma(const __half* __restrict__ A, const __half* __restrict__ Wh,
                            __half* __restrict__ out) {
    constexpr int BM = 64, K = 128;
    constexpr int LDA = K + 8;    // padded strides: +16B per row -> bank-spread
    constexpr int LDW = BN + 8;
    constexpr int NWARP = 4 * (BN / 64);
    constexpr int NT = NWARP * 32;
    extern __shared__ __half dyn[];
    __half* sA = dyn;                   // BM * LDA
    __half* sW = dyn + BM * LDA;        // K * LDW

    const int tid = threadIdx.x;
    const int wid = tid >> 5, lane = tid & 31;
    const int wm = wid & 3, wn = wid >> 2;
    const int rowBase = blockIdx.x * BM;

    for (int i = tid; i < BM * K / 8; i += NT) {
        int r = i >> 4;
        int c = (i & 15) * 8;
        int row = min(rowBase + r, NN - 1);
        *(uint4*)&sA[r * LDA + c] = *(const uint4*)&A[(size_t)row * K + c];
    }
    for (int i = tid; i < K * BN / 8; i += NT) {
        int r = i / (BN / 8);
        int c = (i % (BN / 8)) * 8;
        *(uint4*)&sW[r * LDW + c] = *(const uint4*)&Wh[(size_t)r * BN + c];
    }
    __syncthreads();

    wmma::fragment<wmma::accumulator, 16, 16, 16, float> c[4];
    #pragma unroll
    for (int n = 0; n < 4; n++) wmma::fill_fragment(c[n], 0.f);

    #pragma unroll
    for (int k = 0; k < K; k += 16) {
        wmma::fragment<wmma::matrix_a, 16, 16, 16, __half, wmma::row_major> a;
        wmma::load_matrix_sync(a, &sA[(wm * 16) * LDA + k], LDA);
        #pragma unroll
        for (int n = 0; n < 4; n++) {
            wmma::fragment<wmma::matrix_b, 16, 16, 16, __half, wmma::row_major> b;
            wmma::load_matrix_sync(b, &sW[k * LDW + wn * 64 + n * 16], LDW);
            wmma::mma_sync(c[n], a, b, c[n]);
        }
    }
    __syncthreads();  // done with sW; reuse as fp32 staging

    float* stage = (float*)sW + (size_t)wid * 16 * 64;  // 4KB per warp
    #pragma unroll
    for (int n = 0; n < 4; n++)
        wmma::store_matrix_sync(stage + n * 16, c[n], 64, wmma::mem_row_major);
    __syncwarp();

    for (int i = lane; i < 128; i += 32) {
        int r = i >> 3;
        int cc = (i & 7) * 8;
        int row = rowBase + wm * 16 + r;
        if (row < NN) {
            float dv = d_dinv[row];
            __half2 hv[4];
            #pragma unroll
            for (int q = 0; q < 4; q++) {
                float v0 = stage[r * 64 + cc + 2 * q] * dv;
                float v1 = stage[r * 64 + cc + 2 * q + 1] * dv;
                hv[q] = __floats2half2_rn(v0, v1);
            }
            *(uint4*)&out[(size_t)row * BN + wn * 64 + cc] = *(uint4*)hv;
        }
    }
}

// ---------------- layer-1 aggregate: warp per node, 128 cols fp16 ------------
__global__ void k_gather1(const float* __restrict__ b1) {
    int warp = (blockIdx.x * blockDim.x + threadIdx.x) >> 5;
    int lane = threadIdx.x & 31;
    if (warp >= NN) return;
    const uint2* g = (const uint2*)d_g;
    uint2 sv = g[(size_t)warp * 32 + lane];
    float2 f0 = __half22float2(*(__half2*)&sv.x);
    float2 f1 = __half22float2(*(__half2*)&sv.y);
    float4 acc = make_float4(f0.x, f0.y, f1.x, f1.y);  // self-loop term
    int s = d_off[warp], e = d_off[warp + 1];
    for (int i = s; i < e; i += 32) {
        int u = (i + lane < e) ? d_srcl[i + lane] : 0;
        int m = min(32, e - i);
        for (int j = 0; j < m; j++) {
            int uu = __shfl_sync(0xffffffffu, u, j);
            uint2 tv = g[(size_t)uu * 32 + lane];
            float2 t0 = __half22float2(*(__half2*)&tv.x);
            float2 t1 = __half22float2(*(__half2*)&tv.y);
            acc.x += t0.x; acc.y += t0.y; acc.z += t1.x; acc.w += t1.y;
        }
    }
    float dv = d_dinv[warp];
    float4 bb = ((const float4*)b1)[lane];
    __half2 h0 = __floats2half2_rn(fmaxf(dv * acc.x + bb.x, 0.f),
                                   fmaxf(dv * acc.y + bb.y, 0.f));
    __half2 h1 = __floats2half2_rn(fmaxf(dv * acc.z + bb.z, 0.f),
                                   fmaxf(dv * acc.w + bb.w, 0.f));
    uint2 o;
    o.x = *(unsigned*)&h0;
    o.y = *(unsigned*)&h1;
    ((uint2*)d_xh)[(size_t)warp * 32 + lane] = o;  // h1 fp16 over xh
}

// ---------------- layer-2 aggregate: warp per node, 64 cols fp16 -------------
__global__ void k_gather2(const float* __restrict__ b2) {
    int warp = (blockIdx.x * blockDim.x + threadIdx.x) >> 5;
    int lane = threadIdx.x & 31;
    if (warp >= NN) return;
    const unsigned* g = (const unsigned*)d_g;
    float2 acc = __half22float2(*(__half2*)&g[(size_t)warp * 32 + lane]);
    int s = d_off[warp], e = d_off[warp + 1];
    for (int i = s; i < e; i += 32) {
        int u = (i + lane < e) ? d_srcl[i + lane] : 0;
        int m = min(32, e - i);
        for (int j = 0; j < m; j++) {
            int uu = __shfl_sync(0xffffffffu, u, j);
            unsigned tv = g[(size_t)uu * 32 + lane];
            float2 t = __half22float2(*(__half2*)&tv);
            acc.x += t.x; acc.y += t.y;
        }
    }
    float dv = d_dinv[warp];
    float2 bb = ((const float2*)b2)[lane];
    __half2 zz = __floats2half2_rn(dv * acc.x + bb.x, dv * acc.y + bb.y);
    ((unsigned*)d_z)[(size_t)warp * 32 + lane] = *(unsigned*)&zz;
}

// ---------------- decoder: 4 lanes per edge, fp16 z, fp32 accumulate ---------
__global__ void k_decode(const int* __restrict__ pos32, const int* __restrict__ neg32,
                         float* __restrict__ out) {
    long long gt = (long long)blockIdx.x * blockDim.x + threadIdx.x;
    long long e = gt >> 2;
    int sub = threadIdx.x & 3;
    if (e >= 2LL * NE) return;
    const int* p;
    long long ee;
    float* o;
    if (e < NE) { p = pos32; ee = e; o = out; }
    else        { p = neg32; ee = e - NE; o = out + NE; }
    int flag = d_flag;
    int s = ld_idx(p, ee, flag);
    int d = ld_idx(p, NE + ee, flag);
    const uint4* z4 = (const uint4*)d_z;  // node row = 8 uint4 (64 halves)
    uint4 a0 = z4[(size_t)s * 8 + sub * 2];
    uint4 a1 = z4[(size_t)s * 8 + sub * 2 + 1];
    uint4 c0 = z4[(size_t)d * 8 + sub * 2];
    uint4 c1 = z4[(size_t)d * 8 + sub * 2 + 1];
    const __half2* ah0 = reinterpret_cast<const __half2*>(&a0);
    const __half2* ah1 = reinterpret_cast<const __half2*>(&a1);
    const __half2* ch0 = reinterpret_cast<const __half2*>(&c0);
    const __half2* ch1 = reinterpret_cast<const __half2*>(&c1);
    float pr = 0.f;
    #pragma unroll
    for (int i = 0; i < 4; i++) {
        float2 fa = __half22float2(ah0[i]);
        float2 fc = __half22float2(ch0[i]);
        pr += fa.x * fc.x + fa.y * fc.y;
        float2 ga = __half22float2(ah1[i]);
        float2 gc = __half22float2(ch1[i]);
        pr += ga.x * gc.x + ga.y * gc.y;
    }
    pr += __shfl_down_sync(0xffffffffu, pr, 2, 4);
    pr += __shfl_down_sync(0xffffffffu, pr, 1, 4);
    if (sub == 0) o[ee] = pr;
}

// ---------------- launch ------------------------------------------------------
extern "C" void kernel_launch(void* const* d_in, const int* in_sizes, int n_in,
                              void* d_out, int out_size) {
    const float* x     = (const float*)d_in[0];
    const int*   pos32 = (const int*)d_in[1];
    const int*   neg32 = (const int*)d_in[2];
    const float* W1    = (const float*)d_in[3];
    const float* b1    = (const float*)d_in[4];
    const float* W2    = (const float*)d_in[5];
    const float* b2    = (const float*)d_in[6];
    float* out = (float*)d_out;

    __half *xh, *g, *z, *w1h, *w2h;
    cudaGetSymbolAddress((void**)&xh,  d_xh);
    cudaGetSymbolAddress((void**)&g,   d_g);
    cudaGetSymbolAddress((void**)&z,   d_z);
    cudaGetSymbolAddress((void**)&w1h, d_w1h);
    cudaGetSymbolAddress((void**)&w2h, d_w2h);

    // dynamic smem sizes for the padded wmma kernels
    const int smem1 = (64 * (128 + 8) + 128 * (128 + 8)) * (int)sizeof(__half);  // 52224
    const int smem2 = (64 * (128 + 8) + 128 * (64 + 8))  * (int)sizeof(__half);  // 35840
    cudaFuncSetAttribute(k_gemm_wmma<128>, cudaFuncAttributeMaxDynamicSharedMemorySize, smem1);
    cudaFuncSetAttribute(k_gemm_wmma<64>,  cudaFuncAttributeMaxDynamicSharedMemorySize, smem2);

    const int nscan = (NN + 1023) / 1024;  // 98

    cudaStream_t cap = cudaStreamPerThread;
    cudaStream_t s2;
    cudaStreamCreate(&s2);
    cudaEvent_t e0, e_conv, e_scan, e_fill;
    cudaEventCreateWithFlags(&e0,     cudaEventDisableTiming);
    cudaEventCreateWithFlags(&e_conv, cudaEventDisableTiming);
    cudaEventCreateWithFlags(&e_scan, cudaEventDisableTiming);
    cudaEventCreateWithFlags(&e_fill, cudaEventDisableTiming);

    // side stream: x -> fp16 (DRAM-bound), overlaps CSR chain
    cudaEventRecord(e0, cap);
    cudaStreamWaitEvent(s2, e0, 0);
    k_convx<<<(NN * 128 / 8 + 255) / 256, 256, 0, s2>>>(x);
    cudaEventRecord(e_conv, s2);

    // main: fused pre (init_deg + convw + detect) -> degree -> scans
    k_pre<<<(NN + 255) / 256, 256, 0, cap>>>(pos32, W1, W2);
    k_degree<<<(NE + 255) / 256, 256, 0, cap>>>(pos32);
    k_scan1<<<nscan, 1024, 0, cap>>>();
    k_scan23<<<(NN + 255) / 256, 256, 0, cap>>>(nscan);
    cudaEventRecord(e_scan, cap);

    // side: fill (atomic/L2-bound) overlaps GEMM1 (tensor-bound)
    cudaStreamWaitEvent(s2, e_scan, 0);
    k_fill<<<(NE + 255) / 256, 256, 0, s2>>>(pos32);
    cudaEventRecord(e_fill, s2);

    // main: GEMM1 g1 = dinv * (x @ W1) fp16
    cudaStreamWaitEvent(cap, e_conv, 0);
    k_gemm_wmma<128><<<(NN + 63) / 64, 256, smem1, cap>>>(xh, w1h, g);

    cudaStreamWaitEvent(cap, e_fill, 0);
    // h1 = relu(dinv*agg + b1) fp16 -> xh
    k_gather1<<<(NN * 32 + 255) / 256, 256, 0, cap>>>(b1);

    // GEMM2 + gather2
    k_gemm_wmma<64><<<(NN + 63) / 64, 128, smem2, cap>>>(xh, w2h, g);
    k_gather2<<<(NN * 32 + 255) / 256, 256, 0, cap>>>(b2);

    // decode
    long long tot = 2LL * NE * 4;
    k_decode<<<(unsigned)((tot + 255) / 256), 256, 0, cap>>>(pos32, neg32, out);

    cudaEventDestroy(e0);
    cudaEventDestroy(e_conv);
    cudaEventDestroy(e_scan);
    cudaEventDestroy(e_fill);
    cudaStreamDestroy(s2);
}